// round 4
// baseline (speedup 1.0000x reference)
#include <cuda_runtime.h>
#include <cstdint>

// VolumeRenderer via TMA bulk-copy pipeline.
// alpha: [R,128,1] f32, rgbs: [R,128,3] f32 -> out [R,3] f32.
//
// Each chunk = 16 consecutive rays: alpha 8KB + rgbs 24KB, both contiguous.
// 3-stage cp.async.bulk -> SMEM pipeline (mbarrier complete_tx), persistent
// CTAs. 8 warps/CTA, each warp computes 2 rays per chunk from SMEM
// (interleaved scan chains for ILP). Loads are decoupled from the shfl
// dependency chains, keeping DRAM saturated.

#define EPS 1e-10f
#define RAYS_PER_CHUNK 16
#define NSTAGES 3
#define THREADS 256

#define ALPHA_CHUNK_FLOATS (RAYS_PER_CHUNK * 128)   // 2048 f32 = 8KB
#define RGB_CHUNK_FLOATS   (RAYS_PER_CHUNK * 384)   // 6144 f32 = 24KB
#define STAGE_FLOATS       (ALPHA_CHUNK_FLOATS + RGB_CHUNK_FLOATS)
#define STAGE_BYTES        (STAGE_FLOATS * 4)        // 32KB
#define SMEM_DATA_OFF      128
#define SMEM_TOTAL         (SMEM_DATA_OFF + NSTAGES * STAGE_BYTES)

__device__ __forceinline__ uint32_t smem_u32(const void* p) {
    uint32_t a;
    asm("{ .reg .u64 t; cvta.to.shared.u64 t, %1; cvt.u32.u64 %0, t; }" : "=r"(a) : "l"(p));
    return a;
}

__device__ __forceinline__ void mbar_init(uint32_t mbar, uint32_t count) {
    asm volatile("mbarrier.init.shared.b64 [%0], %1;" :: "r"(mbar), "r"(count) : "memory");
}

__device__ __forceinline__ void mbar_expect_tx(uint32_t mbar, uint32_t bytes) {
    asm volatile("mbarrier.arrive.expect_tx.shared.b64 _, [%0], %1;"
                 :: "r"(mbar), "r"(bytes) : "memory");
}

__device__ __forceinline__ void mbar_wait(uint32_t mbar, uint32_t parity) {
    asm volatile(
        "{\n\t"
        ".reg .pred P;\n\t"
        "WAIT_%=:\n\t"
        "mbarrier.try_wait.parity.acquire.cta.shared::cta.b64 P, [%0], %1, 0x989680;\n\t"
        "@P bra.uni DONE_%=;\n\t"
        "bra.uni WAIT_%=;\n\t"
        "DONE_%=:\n\t"
        "}"
        :: "r"(mbar), "r"(parity) : "memory");
}

__device__ __forceinline__ void bulk_g2s(uint32_t dst, const void* src,
                                         uint32_t bytes, uint32_t mbar) {
    asm volatile(
        "cp.async.bulk.shared::cluster.global.mbarrier::complete_tx::bytes "
        "[%0], [%1], %2, [%3];"
        :: "r"(dst), "l"(src), "r"(bytes), "r"(mbar) : "memory");
}

__global__ __launch_bounds__(THREADS, 2) void volume_render_tma(
    const float* __restrict__ alpha,
    const float* __restrict__ rgbs,
    float* __restrict__ out,
    int R, int nchunks)
{
    extern __shared__ __align__(128) unsigned char smem_raw[];
    float* data = reinterpret_cast<float*>(smem_raw + SMEM_DATA_OFF);
    const uint32_t smem_base = smem_u32(smem_raw);

    const int tid = threadIdx.x;
    const int wid = tid >> 5;
    const int lane = tid & 31;
    const int nblocks = gridDim.x;

    // ---- init mbarriers ----
    if (tid == 0) {
        #pragma unroll
        for (int s = 0; s < NSTAGES; s++) mbar_init(smem_base + s * 8, 1);
        asm volatile("fence.proxy.async.shared::cta;" ::: "memory");
    }
    __syncthreads();

    // ---- issue helper (thread 0 only) ----
    auto issue = [&](int stage, int chunk) {
        const int base = chunk * RAYS_PER_CHUNK;
        const int nr = (R - base < RAYS_PER_CHUNK) ? (R - base) : RAYS_PER_CHUNK;
        const uint32_t abytes = (uint32_t)nr * 512u;
        const uint32_t rbytes = (uint32_t)nr * 1536u;
        const uint32_t mbar = smem_base + stage * 8;
        const uint32_t dst = smem_base + SMEM_DATA_OFF + stage * STAGE_BYTES;
        mbar_expect_tx(mbar, abytes + rbytes);
        bulk_g2s(dst, alpha + (size_t)base * 128, abytes, mbar);
        bulk_g2s(dst + ALPHA_CHUNK_FLOATS * 4, rgbs + (size_t)base * 384, rbytes, mbar);
    };

    // ---- prologue: fill pipeline ----
    if (tid == 0) {
        #pragma unroll
        for (int s = 0; s < NSTAGES; s++) {
            const int chunk = blockIdx.x + s * nblocks;
            if (chunk < nchunks) issue(s, chunk);
        }
    }

    // ---- main loop ----
    for (int k = 0;; k++) {
        const int chunk = blockIdx.x + k * nblocks;
        if (chunk >= nchunks) break;
        const int stage = k % NSTAGES;
        const uint32_t parity = (uint32_t)((k / NSTAGES) & 1);

        mbar_wait(smem_base + stage * 8, parity);

        const float* abuf = data + stage * STAGE_FLOATS;
        const float* rbuf = abuf + ALPHA_CHUNK_FLOATS;

        const int la = wid * 2;           // local ray A in chunk
        const int lb = la + 1;            // local ray B
        const size_t gA = (size_t)chunk * RAYS_PER_CHUNK + la;
        const size_t gB = gA + 1;
        const bool vA = (gA < (size_t)R);
        const bool vB = (gB < (size_t)R);

        // SMEM loads (conflict-free per 8-lane phase)
        float4 aA = make_float4(0.f, 0.f, 0.f, 0.f), aB = aA;
        float4 rA0 = aA, rA1 = aA, rA2 = aA, rB0 = aA, rB1 = aA, rB2 = aA;
        if (vA) {
            aA = *(reinterpret_cast<const float4*>(abuf + la * 128) + lane);
            const float4* p = reinterpret_cast<const float4*>(rbuf + la * 384) + lane * 3;
            rA0 = p[0]; rA1 = p[1]; rA2 = p[2];
        }
        if (vB) {
            aB = *(reinterpret_cast<const float4*>(abuf + lb * 128) + lane);
            const float4* p = reinterpret_cast<const float4*>(rbuf + lb * 384) + lane * 3;
            rB0 = p[0]; rB1 = p[1]; rB2 = p[2];
        }

        const float tA0 = 1.0f - aA.x + EPS, tA1 = 1.0f - aA.y + EPS;
        const float tA2 = 1.0f - aA.z + EPS, tA3 = 1.0f - aA.w + EPS;
        const float tB0 = 1.0f - aB.x + EPS, tB1 = 1.0f - aB.y + EPS;
        const float tB2 = 1.0f - aB.z + EPS, tB3 = 1.0f - aB.w + EPS;

        float inclA = (tA0 * tA1) * (tA2 * tA3);
        float inclB = (tB0 * tB1) * (tB2 * tB3);

        #pragma unroll
        for (int off = 1; off < 32; off <<= 1) {
            const float xA = __shfl_up_sync(0xffffffffu, inclA, off);
            const float xB = __shfl_up_sync(0xffffffffu, inclB, off);
            if (lane >= off) { inclA *= xA; inclB *= xB; }
        }
        float exclA = __shfl_up_sync(0xffffffffu, inclA, 1);
        float exclB = __shfl_up_sync(0xffffffffu, inclB, 1);
        if (lane == 0) { exclA = 1.0f; exclB = 1.0f; }

        float aacc0 = 0.f, aacc1 = 0.f, aacc2 = 0.f;
        {
            float tr = exclA, w;
            w = tr * aA.x; aacc0 = fmaf(w, rA0.x, aacc0); aacc1 = fmaf(w, rA0.y, aacc1); aacc2 = fmaf(w, rA0.z, aacc2); tr *= tA0;
            w = tr * aA.y; aacc0 = fmaf(w, rA0.w, aacc0); aacc1 = fmaf(w, rA1.x, aacc1); aacc2 = fmaf(w, rA1.y, aacc2); tr *= tA1;
            w = tr * aA.z; aacc0 = fmaf(w, rA1.z, aacc0); aacc1 = fmaf(w, rA1.w, aacc1); aacc2 = fmaf(w, rA2.x, aacc2); tr *= tA2;
            w = tr * aA.w; aacc0 = fmaf(w, rA2.y, aacc0); aacc1 = fmaf(w, rA2.z, aacc1); aacc2 = fmaf(w, rA2.w, aacc2);
        }
        float bacc0 = 0.f, bacc1 = 0.f, bacc2 = 0.f;
        {
            float tr = exclB, w;
            w = tr * aB.x; bacc0 = fmaf(w, rB0.x, bacc0); bacc1 = fmaf(w, rB0.y, bacc1); bacc2 = fmaf(w, rB0.z, bacc2); tr *= tB0;
            w = tr * aB.y; bacc0 = fmaf(w, rB0.w, bacc0); bacc1 = fmaf(w, rB1.x, bacc1); bacc2 = fmaf(w, rB1.y, bacc2); tr *= tB1;
            w = tr * aB.z; bacc0 = fmaf(w, rB1.z, bacc0); bacc1 = fmaf(w, rB1.w, bacc1); bacc2 = fmaf(w, rB2.x, bacc2); tr *= tB2;
            w = tr * aB.w; bacc0 = fmaf(w, rB2.y, bacc0); bacc1 = fmaf(w, rB2.z, bacc1); bacc2 = fmaf(w, rB2.w, bacc2);
        }

        #pragma unroll
        for (int off = 16; off > 0; off >>= 1) {
            aacc0 += __shfl_xor_sync(0xffffffffu, aacc0, off);
            aacc1 += __shfl_xor_sync(0xffffffffu, aacc1, off);
            aacc2 += __shfl_xor_sync(0xffffffffu, aacc2, off);
            bacc0 += __shfl_xor_sync(0xffffffffu, bacc0, off);
            bacc1 += __shfl_xor_sync(0xffffffffu, bacc1, off);
            bacc2 += __shfl_xor_sync(0xffffffffu, bacc2, off);
        }

        if (vA && lane < 3) {
            const float v = (lane == 0) ? aacc0 : ((lane == 1) ? aacc1 : aacc2);
            out[gA * 3 + lane] = v;
        } else if (vB && lane >= 3 && lane < 6) {
            const int c = lane - 3;
            const float v = (c == 0) ? bacc0 : ((c == 1) ? bacc1 : bacc2);
            out[gB * 3 + c] = v;
        }

        // all warps done reading this stage -> safe to refill
        __syncthreads();
        const int nextChunk = chunk + NSTAGES * nblocks;
        if (tid == 0 && nextChunk < nchunks) issue(stage, nextChunk);
    }
}

extern "C" void kernel_launch(void* const* d_in, const int* in_sizes, int n_in,
                              void* d_out, int out_size)
{
    const float* alpha = (const float*)d_in[0];   // [R,128,1]
    const float* rgbs  = (const float*)d_in[1];   // [R,128,3]
    float* out = (float*)d_out;                   // [R,3]

    const int R = in_sizes[0] / 128;
    const int nchunks = (R + RAYS_PER_CHUNK - 1) / RAYS_PER_CHUNK;

    int blocks = 152 * 2;                 // persistent: 2 CTAs/SM (96KB smem each)
    if (blocks > nchunks) blocks = nchunks;

    cudaFuncSetAttribute(volume_render_tma,
                         cudaFuncAttributeMaxDynamicSharedMemorySize, SMEM_TOTAL);

    volume_render_tma<<<blocks, THREADS, SMEM_TOTAL>>>(alpha, rgbs, out, R, nchunks);
}

// round 5
// speedup vs baseline: 1.0702x; 1.0702x over previous
#include <cuda_runtime.h>
#include <cstdint>

// VolumeRenderer: per-ray exclusive-cumprod transmittance * alpha, dot with rgb.
// alpha: [R,128,1] f32, rgbs: [R,128,3] f32 -> out [R,3] f32.
//
// One warp per ray. Alpha: lane l loads samples [4l,4l+4) (coalesced float4).
// Weights (excl-cumprod * alpha) computed via warp scan, staged in SMEM.
// RGB: loaded FULLY COALESCED (lane l -> float4 l, l+32, l+64 of the ray's
// 96-float4 block; each LDG = 512B contiguous = 4 lines instead of 12),
// weights fetched per-float from SMEM, channel resolved by lane%3 rotation.

#define EPS 1e-10f

__global__ __launch_bounds__(256) void volume_render_coal(
    const float* __restrict__ alpha,
    const float* __restrict__ rgbs,
    float* __restrict__ out,
    int R)
{
    __shared__ float4 w_smem[8 * 32];   // 8 warps x 128 weights (4KB)

    const int warp_id = (blockIdx.x * blockDim.x + threadIdx.x) >> 5;
    const int wid = threadIdx.x >> 5;
    const int lane = threadIdx.x & 31;
    if (warp_id >= R) return;

    const size_t ray = (size_t)warp_id;

    // ---- coalesced rgb loads: 3 x (512B contiguous per instruction) ----
    const float4* rgb4 = reinterpret_cast<const float4*>(rgbs + ray * 384);
    const float4 v0 = rgb4[lane];        // floats [4*lane      , +4)
    const float4 v1 = rgb4[lane + 32];   // floats [4*lane + 128, +4)
    const float4 v2 = rgb4[lane + 64];   // floats [4*lane + 256, +4)

    // ---- alpha load + transmittance scan ----
    const float4 a4 = *(reinterpret_cast<const float4*>(alpha + ray * 128) + lane);

    const float t0 = 1.0f - a4.x + EPS;
    const float t1 = 1.0f - a4.y + EPS;
    const float t2 = 1.0f - a4.z + EPS;
    const float t3 = 1.0f - a4.w + EPS;

    float incl = (t0 * t1) * (t2 * t3);
    #pragma unroll
    for (int off = 1; off < 32; off <<= 1) {
        const float v = __shfl_up_sync(0xffffffffu, incl, off);
        if (lane >= off) incl *= v;
    }
    float excl = __shfl_up_sync(0xffffffffu, incl, 1);
    if (lane == 0) excl = 1.0f;

    // per-sample weights for this lane's 4 samples
    float4 wv;
    {
        float tr = excl;
        wv.x = tr * a4.x; tr *= t0;
        wv.y = tr * a4.y; tr *= t1;
        wv.z = tr * a4.z; tr *= t2;
        wv.w = tr * a4.w;
    }

    // stage weights: w_all[s] = weight of sample s (s = 4*lane + k)
    w_smem[wid * 32 + lane] = wv;
    __syncwarp();
    const float* w_all = reinterpret_cast<const float*>(&w_smem[wid * 32]);

    // ---- weighted accumulation from coalesced rgb values ----
    // float f = 4*lane + 128*t + i  ->  sample s = f/3, channel c = f%3.
    // c = (lane%3 + o)%3 with o = (2t+i)%3 compile-time; accumulate into b[o],
    // rotate at the end.
    const int fb = 4 * lane;
    float b0 = 0.f, b1 = 0.f, b2 = 0.f;

    {   // t = 0: o(i) = 0,1,2,0
        const int f0 = fb;
        b0 = fmaf(w_all[(f0 + 0) / 3], v0.x, b0);
        b1 = fmaf(w_all[(f0 + 1) / 3], v0.y, b1);
        b2 = fmaf(w_all[(f0 + 2) / 3], v0.z, b2);
        b0 = fmaf(w_all[(f0 + 3) / 3], v0.w, b0);
    }
    {   // t = 1: o(i) = 2,0,1,2
        const int f0 = fb + 128;
        b2 = fmaf(w_all[(f0 + 0) / 3], v1.x, b2);
        b0 = fmaf(w_all[(f0 + 1) / 3], v1.y, b0);
        b1 = fmaf(w_all[(f0 + 2) / 3], v1.z, b1);
        b2 = fmaf(w_all[(f0 + 3) / 3], v1.w, b2);
    }
    {   // t = 2: o(i) = 1,2,0,1
        const int f0 = fb + 256;
        b1 = fmaf(w_all[(f0 + 0) / 3], v2.x, b1);
        b2 = fmaf(w_all[(f0 + 1) / 3], v2.y, b2);
        b0 = fmaf(w_all[(f0 + 2) / 3], v2.z, b0);
        b1 = fmaf(w_all[(f0 + 3) / 3], v2.w, b1);
    }

    // rotate (b0,b1,b2) by r = lane%3: acc_c = b[(c - r + 3) % 3]
    const int r = lane % 3;
    float acc0, acc1, acc2;
    if (r == 0)      { acc0 = b0; acc1 = b1; acc2 = b2; }
    else if (r == 1) { acc0 = b2; acc1 = b0; acc2 = b1; }
    else             { acc0 = b1; acc1 = b2; acc2 = b0; }

    // ---- butterfly reduce 3 channels across the warp ----
    #pragma unroll
    for (int off = 16; off > 0; off >>= 1) {
        acc0 += __shfl_xor_sync(0xffffffffu, acc0, off);
        acc1 += __shfl_xor_sync(0xffffffffu, acc1, off);
        acc2 += __shfl_xor_sync(0xffffffffu, acc2, off);
    }

    if (lane < 3) {
        const float v = (lane == 0) ? acc0 : ((lane == 1) ? acc1 : acc2);
        out[ray * 3 + lane] = v;
    }
}

extern "C" void kernel_launch(void* const* d_in, const int* in_sizes, int n_in,
                              void* d_out, int out_size)
{
    const float* alpha = (const float*)d_in[0];   // [R,128,1]
    const float* rgbs  = (const float*)d_in[1];   // [R,128,3]
    float* out = (float*)d_out;                   // [R,3]

    const int R = in_sizes[0] / 128;

    const int threads = 256;              // 8 warps/block = 8 rays/block
    const int rays_per_block = threads / 32;
    const int blocks = (R + rays_per_block - 1) / rays_per_block;

    volume_render_coal<<<blocks, threads>>>(alpha, rgbs, out, R);
}